// round 5
// baseline (speedup 1.0000x reference)
#include <cuda_runtime.h>
#include <mma.h>
using namespace nvcuda;

// Problem constants
#define Gn    128
#define NPGn  512
#define Hn    128
#define Vn    64
#define EPGn  8192
#define Nn    (Gn * NPGn)      // 65536
#define En    (Gn * EPGn)      // 1048576
#define OUTn  10
#define PSLICES 4

// ---------------- scratch (device globals; no allocation allowed) -----------
__device__ float g_Wf[Hn * Hn];
__device__ float g_bf[Hn];
__device__ float g_h1[(size_t)Nn * Hn];          // 32 MB
__device__ float g_h2[(size_t)Nn * Hn];          // 32 MB
__device__ float g_poolPart[PSLICES][(size_t)Gn * Vn * Hn]; // 16 MB
__device__ float g_virt[(size_t)Gn * Vn * Hn];   // 4 MB
__device__ float g_virt2[(size_t)Gn * Vn * Hn];  // 4 MB
__device__ int   g_csr[En];                      // 4 MB   per-dst sorted src
__device__ int   g_rows[Gn * (NPGn + 1)];        // row_start per graph
__device__ float g_dinv[Nn];

// ---------------- prep: W_f = W_emb @ W_gcn, b_f = b_emb @ W_gcn ------------
__global__ __launch_bounds__(128) void prep_wf(
    const float* __restrict__ W_emb, const float* __restrict__ b_emb,
    const float* __restrict__ W_gcn)
{
    __shared__ float arow[128];
    int m = blockIdx.x;            // 0..128 (128 == bias row)
    int n = threadIdx.x;
    const float* src = (m < 128) ? (W_emb + m * 128) : b_emb;
    arow[n] = src[n];
    __syncthreads();
    float acc = 0.0f;
#pragma unroll 8
    for (int k = 0; k < 128; k++)
        acc = fmaf(arow[k], W_gcn[k * 128 + n], acc);
    if (m < 128) g_Wf[m * 128 + n] = acc;
    else         g_bf[n] = acc;
}

// ---------------- cp.async helpers ------------------------------------------
__device__ __forceinline__ void cp_async16(void* smem_dst, const void* gmem_src) {
    unsigned saddr = (unsigned)__cvta_generic_to_shared(smem_dst);
    asm volatile("cp.async.ca.shared.global [%0], [%1], 16;\n"
                 :: "r"(saddr), "l"(gmem_src));
}
__device__ __forceinline__ void cp_async_commit() {
    asm volatile("cp.async.commit_group;\n");
}
template <int N>
__device__ __forceinline__ void cp_async_wait() {
    asm volatile("cp.async.wait_group %0;\n" :: "n"(N));
}

// ---------------- tf32 tensor-core GEMM: C[M,128]=A[M,128]@B[128,128]+bias --
#define SG_AS(st)      (sm_dyn + (st) * 128 * 36)                   // [128][36]
#define SG_BS(st)      (sm_dyn + 2 * 128 * 36 + (st) * 32 * 132)    // [32][132]
#define SG_BIAS        (sm_dyn + 2 * 128 * 36 + 2 * 32 * 132)       // [16][132]
#define SGEMM_SMEM     ((2 * 128 * 36 + 2 * 32 * 132 + 16 * 132) * 4)

__global__ __launch_bounds__(256) void sgemm_tc(
    const float* __restrict__ A, const float* __restrict__ B,
    const float* __restrict__ bias, float* __restrict__ C, int relu)
{
    extern __shared__ float sm_dyn[];

    int tid = threadIdx.x;
    int warp = tid >> 5;
    int wm = warp >> 1, wn = warp & 1;
    size_t row0 = (size_t)blockIdx.x * 128;

    float* biasRep = SG_BIAS;
    for (int i = tid; i < 16 * 128; i += 256) {
        int r = i >> 7, c = i & 127;
        biasRep[r * 132 + c] = bias[c];
    }

    auto issue_chunk = [&](int k0, int st) {
        float* as = SG_AS(st);
        float* bs = SG_BS(st);
#pragma unroll
        for (int i = tid; i < 1024; i += 256) {
            int r = i >> 3, c = (i & 7) * 4;
            cp_async16(as + r * 36 + c, A + (row0 + r) * 128 + k0 + c);
        }
#pragma unroll
        for (int i = tid; i < 1024; i += 256) {
            int r = i >> 5, c = (i & 31) * 4;
            cp_async16(bs + r * 132 + c, B + (size_t)(k0 + r) * 128 + c);
        }
        cp_async_commit();
    };

    issue_chunk(0, 0);
    issue_chunk(32, 1);

    __syncthreads();  // biasRep ready
    wmma::fragment<wmma::accumulator, 16, 16, 8, float> acc[2][4];
#pragma unroll
    for (int m = 0; m < 2; m++)
#pragma unroll
        for (int n = 0; n < 4; n++)
            wmma::load_matrix_sync(acc[m][n], biasRep + wn * 64 + n * 16, 132,
                                   wmma::mem_row_major);

#pragma unroll
    for (int it = 0; it < 4; it++) {
        int st = it & 1;
        float* as = SG_AS(st);
        float* bs = SG_BS(st);
        if (it < 3) cp_async_wait<1>(); else cp_async_wait<0>();
        __syncthreads();
#pragma unroll
        for (int kk = 0; kk < 32; kk += 8) {
            wmma::fragment<wmma::matrix_a, 16, 16, 8, wmma::precision::tf32,
                           wmma::row_major> af[2];
            wmma::fragment<wmma::matrix_b, 16, 16, 8, wmma::precision::tf32,
                           wmma::row_major> bf[4];
#pragma unroll
            for (int m = 0; m < 2; m++) {
                wmma::load_matrix_sync(af[m], as + (wm * 32 + m * 16) * 36 + kk, 36);
#pragma unroll
                for (int t = 0; t < af[m].num_elements; t++)
                    af[m].x[t] = wmma::__float_to_tf32(af[m].x[t]);
            }
#pragma unroll
            for (int n = 0; n < 4; n++) {
                wmma::load_matrix_sync(bf[n], bs + kk * 132 + wn * 64 + n * 16, 132);
#pragma unroll
                for (int t = 0; t < bf[n].num_elements; t++)
                    bf[n].x[t] = wmma::__float_to_tf32(bf[n].x[t]);
            }
#pragma unroll
            for (int m = 0; m < 2; m++)
#pragma unroll
                for (int n = 0; n < 4; n++)
                    wmma::mma_sync(acc[m][n], af[m], bf[n], acc[m][n]);
        }
        __syncthreads();
        if (it + 2 < 4) issue_chunk((it + 2) * 32, st);
    }

#pragma unroll
    for (int m = 0; m < 2; m++)
#pragma unroll
        for (int n = 0; n < 4; n++) {
            if (relu) {
#pragma unroll
                for (int t = 0; t < acc[m][n].num_elements; t++)
                    acc[m][n].x[t] = fmaxf(acc[m][n].x[t], 0.0f);
            }
            wmma::store_matrix_sync(C + (row0 + wm * 32 + m * 16) * 128 + wn * 64 + n * 16,
                                    acc[m][n], 128, wmma::mem_row_major);
        }
}

// ---------------- CSR build: one CTA per graph ------------------------------
__global__ __launch_bounds__(1024) void build_csr(
    const int* __restrict__ esrc, const int* __restrict__ edst)
{
    __shared__ int cnt[NPGn];
    __shared__ int row[NPGn + 1];
    int g = blockIdx.x, tid = threadIdx.x;
    int ebase = g * EPGn, nbase = g * NPGn;

    if (tid < NPGn) cnt[tid] = 0;
    __syncthreads();
    for (int e = tid; e < EPGn; e += 1024)
        atomicAdd(&cnt[edst[ebase + e] - nbase], 1);
    __syncthreads();
    if (tid < NPGn) {
        int c = cnt[tid];
        g_dinv[nbase + tid] = rsqrtf((float)(c + 1));
        row[tid + 1] = c;
    }
    if (tid == 0) row[0] = 0;
    __syncthreads();
    for (int off = 1; off < NPGn; off <<= 1) {
        int t = 0;
        if (tid < NPGn && tid >= off) t = row[1 + tid - off];
        __syncthreads();
        if (tid < NPGn && tid >= off) row[1 + tid] += t;
        __syncthreads();
    }
    if (tid < NPGn) cnt[tid] = 0;
    if (tid <= NPGn) g_rows[g * (NPGn + 1) + tid] = row[tid];
    __syncthreads();
    for (int e = tid; e < EPGn; e += 1024) {
        int d = edst[ebase + e] - nbase;
        int s = esrc[ebase + e] - nbase;
        int pos = row[d] + atomicAdd(&cnt[d], 1);
        g_csr[ebase + pos] = s;
    }
}

// ---------------- GCN aggregation: grid (graph, feature-quarter) ------------
// smem: hs 64KB + csr 32KB + row/dinv 4KB => ~100KB -> 2 CTAs/SM.
#define AGG_FQ 32
#define AGG_SMEM ((NPGn * AGG_FQ + EPGn + (NPGn + 1) + NPGn) * 4)
__global__ __launch_bounds__(1024) void gcn_agg(const float* __restrict__ b_gcn)
{
    extern __shared__ char smraw[];
    float* hs    = (float*)smraw;                  // 512*32 floats
    int*   csr_s = (int*)(hs + NPGn * AGG_FQ);     // 8192
    int*   row_s = csr_s + EPGn;                   // 513
    float* dinv  = (float*)(row_s + NPGn + 1);     // 512

    int g = blockIdx.x, q = blockIdx.y;
    int tid = threadIdx.x;
    int ebase = g * EPGn, nbase = g * NPGn;
    int f0 = q * AGG_FQ;

    // copy CSR metadata into shared (coalesced)
    for (int i = tid; i < EPGn; i += 1024) csr_s[i] = g_csr[ebase + i];
    for (int i = tid; i < NPGn + 1; i += 1024) row_s[i] = g_rows[g * (NPGn + 1) + i];
    for (int i = tid; i < NPGn; i += 1024) dinv[i] = g_dinv[nbase + i];
    __syncthreads();

    // stage hs[n][f] = dinv[n] * h1[n][f0+f]
    for (int i = tid; i < NPGn * (AGG_FQ / 4); i += 1024) {
        int n = i >> 3, c = (i & 7) * 4;
        float4 v = *(const float4*)(g_h1 + (size_t)(nbase + n) * Hn + f0 + c);
        float dn = dinv[n];
        v.x *= dn; v.y *= dn; v.z *= dn; v.w *= dn;
        *(float4*)(hs + n * AGG_FQ + c) = v;
    }
    __syncthreads();

    int lane = tid & 31, warp = tid >> 5;
    float b = b_gcn[f0 + lane];
    for (int d = warp; d < NPGn; d += 32) {
        float acc = hs[d * AGG_FQ + lane];      // self loop
        float a1 = 0.f, a2 = 0.f, a3 = 0.f;
        int e = row_s[d], end = row_s[d + 1];
        for (; e + 4 <= end; e += 4) {
            int s0 = csr_s[e], s1 = csr_s[e + 1], s2 = csr_s[e + 2], s3 = csr_s[e + 3];
            acc += hs[s0 * AGG_FQ + lane];
            a1  += hs[s1 * AGG_FQ + lane];
            a2  += hs[s2 * AGG_FQ + lane];
            a3  += hs[s3 * AGG_FQ + lane];
        }
        for (; e < end; e++) acc += hs[csr_s[e] * AGG_FQ + lane];
        acc += (a1 + a2) + a3;
        g_h2[(size_t)(nbase + d) * Hn + f0 + lane] =
            fmaxf(fmaf(dinv[d], acc, b), 0.0f);
    }
}

// ---------------- pooling (tf32, split-K, cp.async pipeline) ----------------
#define PL_ES(st)   (sm_dyn + (st) * 32 * 68)                    // [32][68]
#define PL_HS(st)   (sm_dyn + 2 * 32 * 68 + (st) * 32 * 132)     // [32][132]
#define POOL_SMEM   ((2 * 32 * 68 + 2 * 32 * 132) * 4)           // 51200 B

__global__ __launch_bounds__(256) void pool_tc(const float* __restrict__ ew)
{
    extern __shared__ float sm_dyn[];

    int tid = threadIdx.x;
    int warp = tid >> 5;
    int wm = warp >> 1, wn = warp & 1;
    int g = blockIdx.x, sl = blockIdx.y;
    int nbeg = sl * (NPGn / PSLICES);
    const float* ewg = ew + ((size_t)g * NPGn + nbeg) * Vn;
    const float* hg  = g_h2 + ((size_t)g * NPGn + nbeg) * Hn;

    auto issue_chunk = [&](int n0, int st) {
        float* es = PL_ES(st);
        float* hsm = PL_HS(st);
#pragma unroll
        for (int i = tid; i < 512; i += 256) {
            int k = i >> 4, c = (i & 15) * 4;
            cp_async16(es + k * 68 + c, ewg + (size_t)(n0 + k) * Vn + c);
        }
#pragma unroll
        for (int i = tid; i < 1024; i += 256) {
            int k = i >> 5, c = (i & 31) * 4;
            cp_async16(hsm + k * 132 + c, hg + (size_t)(n0 + k) * Hn + c);
        }
        cp_async_commit();
    };

    issue_chunk(0, 0);
    issue_chunk(32, 1);

    wmma::fragment<wmma::accumulator, 16, 16, 8, float> acc[4];
#pragma unroll
    for (int n = 0; n < 4; n++) wmma::fill_fragment(acc[n], 0.0f);

#pragma unroll
    for (int it = 0; it < 4; it++) {          // 4 chunks of 32 nodes (128 total)
        int st = it & 1;
        float* es = PL_ES(st);
        float* hsm = PL_HS(st);
        if (it < 3) cp_async_wait<1>(); else cp_async_wait<0>();
        __syncthreads();
#pragma unroll
        for (int kk = 0; kk < 32; kk += 8) {
            wmma::fragment<wmma::matrix_a, 16, 16, 8, wmma::precision::tf32,
                           wmma::col_major> af;
            wmma::load_matrix_sync(af, es + kk * 68 + wm * 16, 68);
#pragma unroll
            for (int t = 0; t < af.num_elements; t++)
                af.x[t] = wmma::__float_to_tf32(af.x[t]);
            wmma::fragment<wmma::matrix_b, 16, 16, 8, wmma::precision::tf32,
                           wmma::row_major> bf[4];
#pragma unroll
            for (int n = 0; n < 4; n++) {
                wmma::load_matrix_sync(bf[n], hsm + kk * 132 + wn * 64 + n * 16, 132);
#pragma unroll
                for (int t = 0; t < bf[n].num_elements; t++)
                    bf[n].x[t] = wmma::__float_to_tf32(bf[n].x[t]);
            }
#pragma unroll
            for (int n = 0; n < 4; n++)
                wmma::mma_sync(acc[n], af, bf[n], acc[n]);
        }
        __syncthreads();
        if (it + 2 < 4) issue_chunk((it + 2) * 32, st);
    }

#pragma unroll
    for (int n = 0; n < 4; n++)
        wmma::store_matrix_sync(
            g_poolPart[sl] + ((size_t)g * Vn + wm * 16) * Hn + wn * 64 + n * 16,
            acc[n], 128, wmma::mem_row_major);
}

// ---------------- reduce split-K partials -> g_virt (float4) ----------------
__global__ void reduce_virt()
{
    int idx = blockIdx.x * blockDim.x + threadIdx.x;   // float4 index
    if (idx >= (Gn * Vn * Hn) / 4) return;
    const float4* p0 = (const float4*)g_poolPart[0];
    const float4* p1 = (const float4*)g_poolPart[1];
    const float4* p2 = (const float4*)g_poolPart[2];
    const float4* p3 = (const float4*)g_poolPart[3];
    float4 a = p0[idx], b = p1[idx], c = p2[idx], d = p3[idx];
    float4 o;
    o.x = (a.x + b.x) + (c.x + d.x);
    o.y = (a.y + b.y) + (c.y + d.y);
    o.z = (a.z + b.z) + (c.z + d.z);
    o.w = (a.w + b.w) + (c.w + d.w);
    ((float4*)g_virt)[idx] = o;
}

// ---------------- fused tail: mean_v + 3 chained GEMVs per graph ------------
__global__ __launch_bounds__(128) void tail_kernel(
    const float* __restrict__ vW2, const float* __restrict__ vb2,
    const float* __restrict__ mW1, const float* __restrict__ mb1,
    const float* __restrict__ mW2, const float* __restrict__ mb2,
    float* __restrict__ out)
{
    __shared__ float m2s[128], gfs[128], f1s[128];
    int g = blockIdx.x;
    int n = threadIdx.x;

    const float* vp = g_virt2 + (size_t)g * Vn * Hn + n;
    float s = 0.0f;
#pragma unroll 16
    for (int v = 0; v < Vn; v++) s += vp[(size_t)v * Hn];
    m2s[n] = s * (1.0f / 64.0f);
    __syncthreads();

    float acc = vb2[n];
#pragma unroll 8
    for (int k = 0; k < 128; k++) acc = fmaf(m2s[k], vW2[k * 128 + n], acc);
    gfs[n] = acc;
    __syncthreads();

    acc = mb1[n];
#pragma unroll 8
    for (int k = 0; k < 128; k++) acc = fmaf(gfs[k], mW1[k * 128 + n], acc);
    f1s[n] = fmaxf(acc, 0.0f);
    __syncthreads();

    if (n < OUTn) {
        acc = mb2[n];
#pragma unroll 8
        for (int k = 0; k < 128; k++) acc = fmaf(f1s[k], mW2[k * OUTn + n], acc);
        out[g * OUTn + n] = acc;
    }
}

// ---------------- launch ----------------------------------------------------
extern "C" void kernel_launch(void* const* d_in, const int* in_sizes, int n_in,
                              void* d_out, int out_size)
{
    const float* x     = (const float*)d_in[0];
    const int*   eidx  = (const int*)d_in[1];
    // d_in[2] = batch (unused: graphs contiguous & equal-size)
    const float* W_emb = (const float*)d_in[3];
    const float* b_emb = (const float*)d_in[4];
    const float* W_gcn = (const float*)d_in[5];
    const float* b_gcn = (const float*)d_in[6];
    const float* ew    = (const float*)d_in[7];
    const float* vW1   = (const float*)d_in[8];
    const float* vb1   = (const float*)d_in[9];
    const float* vW2   = (const float*)d_in[10];
    const float* vb2   = (const float*)d_in[11];
    const float* mW1   = (const float*)d_in[12];
    const float* mb1   = (const float*)d_in[13];
    const float* mW2   = (const float*)d_in[14];
    const float* mb2   = (const float*)d_in[15];

    const int* esrc = eidx;
    const int* edst = eidx + En;

    float *p_Wf, *p_bf, *p_h1, *p_virt, *p_virt2;
    cudaGetSymbolAddress((void**)&p_Wf,    g_Wf);
    cudaGetSymbolAddress((void**)&p_bf,    g_bf);
    cudaGetSymbolAddress((void**)&p_h1,    g_h1);
    cudaGetSymbolAddress((void**)&p_virt,  g_virt);
    cudaGetSymbolAddress((void**)&p_virt2, g_virt2);

    cudaFuncSetAttribute(sgemm_tc, cudaFuncAttributeMaxDynamicSharedMemorySize, SGEMM_SMEM);
    cudaFuncSetAttribute(gcn_agg,  cudaFuncAttributeMaxDynamicSharedMemorySize, AGG_SMEM);
    cudaFuncSetAttribute(pool_tc,  cudaFuncAttributeMaxDynamicSharedMemorySize, POOL_SMEM);

    // 0) CSR once (only needs edges)
    build_csr<<<Gn, 1024>>>(esrc, edst);
    // 1) fused pre-aggregation weights (W_f, b_f)
    prep_wf<<<129, 128>>>(W_emb, b_emb, W_gcn);
    // 2) h1 = x @ W_f + b_f                 (tf32 TC, cp.async pipeline)
    sgemm_tc<<<Nn / 128, 256, SGEMM_SMEM>>>(x, p_Wf, p_bf, p_h1, 0);
    // 3) GCN aggregation + b_gcn + relu -> h2   (graph x feature-quarter)
    gcn_agg<<<dim3(Gn, 4), 1024, AGG_SMEM>>>(b_gcn);
    // 4) virtual-node pooling, split-K x4 -> partials, then reduce -> virt
    pool_tc<<<dim3(Gn, PSLICES), 256, POOL_SMEM>>>(ew);
    reduce_virt<<<(Gn * Vn * Hn / 4 + 255) / 256, 256>>>();
    // 5) virt2 = relu(virt @ vW1 + vb1)     (tf32 TC)
    sgemm_tc<<<(Gn * Vn) / 128, 256, SGEMM_SMEM>>>(p_virt, vW1, vb1, p_virt2, 1);
    // 6) fused tail: mean + 3 GEMVs -> out
    tail_kernel<<<Gn, 128>>>(vW2, vb2, mW1, mb1, mW2, mb2, (float*)d_out);
}